// round 7
// baseline (speedup 1.0000x reference)
#include <cuda_runtime.h>
#include <cuda_fp16.h>
#include <cstdint>

#define BB 2
#define NN 4096
#define DD 768

// big-GEMM tiling: CTA 128x256x32, 8 warps (2 M x 4 N) of 64x64
constexpr int BMb = 128, BNb = 256, BKb = 32;
constexpr int STG_A = BMb * BKb * 2;              // 8192 B
constexpr int STG_B = BNb * BKb * 2;              // 16384 B
constexpr int STG   = STG_A + STG_B;              // 24576 B
constexpr int NSTG  = 4;

// QKV tiling (R5/R6 proven): CTA 128x128x32, 8 warps of 64x32
constexpr int BM = 128, BN = 128, BK = 32;

// ---------------------------------------------------------------------------
// Scratch
// ---------------------------------------------------------------------------
__device__ __half g_qh[BB * NN * DD];
__device__ __half g_kh[BB * NN * DD];
__device__ __half g_vh[BB * NN * DD];
__device__ __half g_vt[BB * NN * DD];            // V^T per batch [DD, NN]
__device__ __half g_p[(size_t)BB * NN * NN];     // unnormalized exp(scores), fp16
__device__ float  g_r[BB * NN];                  // 1 / rowsum

// ---------------------------------------------------------------------------
// Helpers
// ---------------------------------------------------------------------------
__device__ __forceinline__ uint32_t smem_u32(const void* p) {
    uint32_t a;
    asm("{ .reg .u64 t; cvta.to.shared.u64 t, %1; cvt.u32.u64 %0, t; }" : "=r"(a) : "l"(p));
    return a;
}
__device__ __forceinline__ uint32_t sw64(uint32_t o) { return o ^ ((o >> 3) & 0x30); }

__device__ __forceinline__ void ldm_x4(uint32_t* r, uint32_t a) {
    asm volatile("ldmatrix.sync.aligned.m8n8.x4.shared.b16 {%0,%1,%2,%3}, [%4];"
                 : "=r"(r[0]), "=r"(r[1]), "=r"(r[2]), "=r"(r[3]) : "r"(a));
}
__device__ __forceinline__ void mma16816(float* c, const uint32_t* a, const uint32_t* b) {
    asm volatile(
        "mma.sync.aligned.m16n8k16.row.col.f32.f16.f16.f32 "
        "{%0,%1,%2,%3},{%4,%5,%6,%7},{%8,%9},{%0,%1,%2,%3};"
        : "+f"(c[0]), "+f"(c[1]), "+f"(c[2]), "+f"(c[3])
        : "r"(a[0]), "r"(a[1]), "r"(a[2]), "r"(a[3]), "r"(b[0]), "r"(b[1]));
}
__device__ __forceinline__ uint32_t h2u(__half2 h) { return *(uint32_t*)&h; }
__device__ __forceinline__ void cpa16(uint32_t dst, const void* src) {
    asm volatile("cp.async.cg.shared.global [%0], [%1], 16;" :: "r"(dst), "l"(src));
}

// ---------------------------------------------------------------------------
// Big GEMM (both operands fp16 K-major):  acc = A[M,K] @ B[N,K]^T
//   MODE 0 (score): C fp16 = exp(alpha * acc)        (unnormalized probs)
//   MODE 1 (pv):    C fp32 = acc * inv[row]          (row normalization)
// 4-stage cp.async pipeline; CTA 128x256x32; warp tile 64x64.
// ---------------------------------------------------------------------------
template <int MODE>
__global__ __launch_bounds__(256, 1)
void gemm_big(const __half* __restrict__ Ag, const __half* __restrict__ Bg,
              void* __restrict__ Cg, const float* __restrict__ inv,
              int Ncols, int K, size_t sAs, size_t sBs, size_t sCs, float alpha)
{
    extern __shared__ __align__(1024) char sm[];

    const int tid  = threadIdx.x;
    const int lane = tid & 31;
    const int warp = tid >> 5;
    const int wm = warp >> 2;      // 0..1 (64 rows)
    const int wn = warp & 3;       // 0..3 (64 cols)
    const int z = blockIdx.z;
    Ag += (size_t)z * sAs;
    Bg += (size_t)z * sBs;
    const int m0 = blockIdx.y * BMb;
    const int n0 = blockIdx.x * BNb;

    float acc[4][8][4];
#pragma unroll
    for (int mi = 0; mi < 4; mi++)
#pragma unroll
        for (int ni = 0; ni < 8; ni++)
#pragma unroll
            for (int r = 0; r < 4; r++) acc[mi][ni][r] = 0.f;

    auto LOAD = [&](int t) {
        const int s = t & (NSTG - 1);
        const int k0 = t * BKb;
        const uint32_t da = smem_u32(sm + s * STG);
        const uint32_t db = da + STG_A;
        // A: 512 x 16B chunks, 2 per thread
#pragma unroll
        for (int i = 0; i < 2; i++) {
            const int idx = tid + i * 256;
            const int r = idx >> 2, c = idx & 3;
            cpa16(da + sw64(r * 64 + c * 16), Ag + (size_t)(m0 + r) * K + k0 + c * 8);
        }
        // B: 1024 x 16B chunks, 4 per thread
#pragma unroll
        for (int i = 0; i < 4; i++) {
            const int idx = tid + i * 256;
            const int r = idx >> 2, c = idx & 3;
            cpa16(db + sw64(r * 64 + c * 16), Bg + (size_t)(n0 + r) * K + k0 + c * 8);
        }
        asm volatile("cp.async.commit_group;" ::: "memory");
    };

    // fragment lane addressing
    const int mrow  = wm * 64 + (lane & 15);
    const int acolb = (lane & 16);
    const int nrow  = wn * 64 + (lane & 7) + ((lane & 16) >> 1);
    const int bcolb = (lane & 8) << 1;

    auto KSTEP = [&](int s, int ks) {
        const uint32_t baseA = smem_u32(sm + s * STG);
        const uint32_t baseB = baseA + STG_A;
        uint32_t a[4][4], b[4][4];
#pragma unroll
        for (int mi = 0; mi < 4; mi++)
            ldm_x4(a[mi], baseA + sw64((mrow + mi * 16) * 64 + ks * 2 + acolb));
#pragma unroll
        for (int n2 = 0; n2 < 4; n2++)
            ldm_x4(b[n2], baseB + sw64((nrow + n2 * 16) * 64 + ks * 2 + bcolb));
#pragma unroll
        for (int mi = 0; mi < 4; mi++)
#pragma unroll
            for (int ni = 0; ni < 8; ni++)
                mma16816(acc[mi][ni], a[mi], &b[ni >> 1][(ni & 1) * 2]);
    };

    const int NT = K / BKb;
    LOAD(0); LOAD(1); LOAD(2);
    for (int t = 0; t < NT; t++) {
        asm volatile("cp.async.wait_group 2;" ::: "memory");
        __syncthreads();
        if (t + 3 < NT) LOAD(t + 3);
        else asm volatile("cp.async.commit_group;" ::: "memory");
        const int s = t & (NSTG - 1);
        KSTEP(s, 0);
        KSTEP(s, 16);
    }

    // ---- epilogue ----
    if (MODE == 0) {
        __half* C = (__half*)Cg + (size_t)z * sCs;
#pragma unroll
        for (int mi = 0; mi < 4; mi++) {
            const int r = m0 + wm * 64 + mi * 16 + (lane >> 2);
#pragma unroll
            for (int ni = 0; ni < 8; ni++) {
                const int c = n0 + wn * 64 + ni * 8 + (lane & 3) * 2;
                *(__half2*)(C + (size_t)r * Ncols + c) =
                    __floats2half2_rn(__expf(alpha * acc[mi][ni][0]),
                                      __expf(alpha * acc[mi][ni][1]));
                *(__half2*)(C + (size_t)(r + 8) * Ncols + c) =
                    __floats2half2_rn(__expf(alpha * acc[mi][ni][2]),
                                      __expf(alpha * acc[mi][ni][3]));
            }
        }
    } else {
        float* C = (float*)Cg + (size_t)z * sCs;
        const float* iv = inv + z * NN;
#pragma unroll
        for (int mi = 0; mi < 4; mi++) {
            const int r = m0 + wm * 64 + mi * 16 + (lane >> 2);
            const float s0 = iv[r], s1 = iv[r + 8];
#pragma unroll
            for (int ni = 0; ni < 8; ni++) {
                const int c = n0 + wn * 64 + ni * 8 + (lane & 3) * 2;
                *(float2*)(C + (size_t)r * Ncols + c) =
                    make_float2(s0 * acc[mi][ni][0], s0 * acc[mi][ni][1]);
                *(float2*)(C + (size_t)(r + 8) * Ncols + c) =
                    make_float2(s1 * acc[mi][ni][2], s1 * acc[mi][ni][3]);
            }
        }
    }
}

// ---------------------------------------------------------------------------
// QKV projection GEMM: C(fp16) = A(fp32 [M,K]) @ B(fp32 [K,N])   (R6-proven)
// ---------------------------------------------------------------------------
__global__ __launch_bounds__(256, 2)
void gemm_qkv(const float* __restrict__ Ag, const float* __restrict__ Bg,
              __half* __restrict__ Cg, int M, int Ncols, int K)
{
    __shared__ __align__(1024) __half sA[2][BM * BK];
    __shared__ __align__(1024) __half sB[2][BN * BK];

    const int tid  = threadIdx.x;
    const int lane = tid & 31;
    const int warp = tid >> 5;
    const int wm = warp >> 2;
    const int wn = warp & 3;
    const int m0 = blockIdx.y * BM;
    const int n0 = blockIdx.x * BN;

    float acc[4][4][4];
#pragma unroll
    for (int mi = 0; mi < 4; mi++)
#pragma unroll
        for (int ni = 0; ni < 4; ni++)
#pragma unroll
            for (int r = 0; r < 4; r++) acc[mi][ni][r] = 0.f;

    float4 fa[4];
    float  fbn[16];
    const int nnf = tid & 127;
    const int q0  = tid >> 7;

    auto LDGA = [&](int t) {
        const int k0 = t * BK;
#pragma unroll
        for (int i = 0; i < 4; i++) {
            const int f = tid + i * 256;
            fa[i] = *(const float4*)(Ag + (size_t)(m0 + (f >> 3)) * K + k0 + (f & 7) * 4);
        }
    };
    auto STSA = [&](int s) {
#pragma unroll
        for (int i = 0; i < 4; i++) {
            const int f = tid + i * 256;
            uint2 u;
            u.x = h2u(__floats2half2_rn(fa[i].x, fa[i].y));
            u.y = h2u(__floats2half2_rn(fa[i].z, fa[i].w));
            *(uint2*)((char*)sA[s] + sw64((f >> 3) * 64 + (f & 7) * 8)) = u;
        }
    };
    auto LDGB = [&](int t) {
        const int k0 = t * BK;
#pragma unroll
        for (int i = 0; i < 4; i++) {
            const int q = q0 + 2 * i;
            const float* src = Bg + (size_t)(k0 + q * 4) * Ncols + n0 + nnf;
            fbn[i * 4 + 0] = src[0];
            fbn[i * 4 + 1] = src[Ncols];
            fbn[i * 4 + 2] = src[2 * Ncols];
            fbn[i * 4 + 3] = src[3 * Ncols];
        }
    };
    auto STSB = [&](int s) {
#pragma unroll
        for (int i = 0; i < 4; i++) {
            const int q = q0 + 2 * i;
            uint2 u;
            u.x = h2u(__floats2half2_rn(fbn[i * 4 + 0], fbn[i * 4 + 1]));
            u.y = h2u(__floats2half2_rn(fbn[i * 4 + 2], fbn[i * 4 + 3]));
            *(uint2*)((char*)sB[s] + sw64(nnf * 64 + q * 8)) = u;
        }
    };

    const int mrow  = wm * 64 + (lane & 15);
    const int acolb = (lane & 16);
    const int nrow  = wn * 32 + (lane & 7) + ((lane & 16) >> 1);
    const int bcolb = (lane & 8) << 1;

    auto KSTEP = [&](int s, int ks) {
        const uint32_t baseA = smem_u32(sA[s]);
        const uint32_t baseB = smem_u32(sB[s]);
        uint32_t a[4][4], b[2][4];
#pragma unroll
        for (int mi = 0; mi < 4; mi++)
            ldm_x4(a[mi], baseA + sw64((mrow + mi * 16) * 64 + ks * 2 + acolb));
#pragma unroll
        for (int n2 = 0; n2 < 2; n2++)
            ldm_x4(b[n2], baseB + sw64((nrow + n2 * 16) * 64 + ks * 2 + bcolb));
#pragma unroll
        for (int mi = 0; mi < 4; mi++)
#pragma unroll
            for (int ni = 0; ni < 4; ni++)
                mma16816(acc[mi][ni], a[mi], &b[ni >> 1][(ni & 1) * 2]);
    };

    LDGA(0); LDGB(0);
    STSA(0); STSB(0);
    __syncthreads();

    const int NT = K / BK;
    for (int t = 0; t < NT; t++) {
        const int s = t & 1;
        const bool more = (t + 1 < NT);
        if (more) LDGA(t + 1);
        KSTEP(s, 0);
        if (more) { STSA(s ^ 1); LDGB(t + 1); }
        KSTEP(s, 16);
        if (more) STSB(s ^ 1);
        __syncthreads();
    }

#pragma unroll
    for (int mi = 0; mi < 4; mi++) {
        const int r = m0 + wm * 64 + mi * 16 + (lane >> 2);
#pragma unroll
        for (int ni = 0; ni < 4; ni++) {
            const int c = n0 + wn * 32 + ni * 8 + (lane & 3) * 2;
            *(__half2*)(Cg + (size_t)r * Ncols + c) =
                __floats2half2_rn(acc[mi][ni][0], acc[mi][ni][1]);
            *(__half2*)(Cg + (size_t)(r + 8) * Ncols + c) =
                __floats2half2_rn(acc[mi][ni][2], acc[mi][ni][3]);
        }
    }
}

// ---------------------------------------------------------------------------
// fp16 transpose per batch: src [NN, DD] -> dst [DD, NN]
// ---------------------------------------------------------------------------
__global__ __launch_bounds__(256)
void transpose_h(const __half* __restrict__ src, __half* __restrict__ dst)
{
    __shared__ __half tile[64][65];
    const int z = blockIdx.z;
    src += (size_t)z * NN * DD;
    dst += (size_t)z * NN * DD;
    const int d0 = blockIdx.x * 64;
    const int t0 = blockIdx.y * 64;
    const int tid = threadIdx.x;

#pragma unroll
    for (int i = 0; i < 8; i++) {
        const int idx = tid + i * 256;
        const int r = idx >> 5, c2 = idx & 31;
        __half2 v = *(const __half2*)(src + (size_t)(t0 + r) * DD + d0 + c2 * 2);
        tile[r][c2 * 2]     = __low2half(v);
        tile[r][c2 * 2 + 1] = __high2half(v);
    }
    __syncthreads();
#pragma unroll
    for (int i = 0; i < 8; i++) {
        const int idx = tid + i * 256;
        const int dr = idx >> 5, c2 = idx & 31;
        __half2 v = __halves2half2(tile[c2 * 2][dr], tile[c2 * 2 + 1][dr]);
        *(__half2*)(dst + (size_t)(d0 + dr) * NN + t0 + c2 * 2) = v;
    }
}

// ---------------------------------------------------------------------------
// Row sums of fp16 probs -> 1/sum (fp32). One block per row of 4096.
// ---------------------------------------------------------------------------
__global__ __launch_bounds__(256)
void rowsum_inv(const __half* __restrict__ P, float* __restrict__ inv)
{
    const __half2* p = (const __half2*)(P + (size_t)blockIdx.x * NN);
    const int t = threadIdx.x;

    float s = 0.f;
#pragma unroll
    for (int i = 0; i < 8; i++) {
        const float2 f = __half22float2(p[t + i * 256]);
        s += f.x + f.y;
    }
    __shared__ float sh[8];
#pragma unroll
    for (int o = 16; o; o >>= 1) s += __shfl_xor_sync(0xffffffffu, s, o);
    if ((t & 31) == 0) sh[t >> 5] = s;
    __syncthreads();
    if (t == 0) {
        float tot = 0.f;
#pragma unroll
        for (int i = 0; i < 8; i++) tot += sh[i];
        inv[blockIdx.x] = 1.0f / tot;
    }
}

// ---------------------------------------------------------------------------
extern "C" void kernel_launch(void* const* d_in, const int* in_sizes, int n_in,
                              void* d_out, int out_size)
{
    const float* x  = (const float*)d_in[0];
    const float* Wq = (const float*)d_in[1];
    const float* Wk = (const float*)d_in[2];
    const float* Wv = (const float*)d_in[3];
    float* out = (float*)d_out;

    __half *qh, *kh, *vh, *vt, *ph;
    float* rv;
    cudaGetSymbolAddress((void**)&qh, g_qh);
    cudaGetSymbolAddress((void**)&kh, g_kh);
    cudaGetSymbolAddress((void**)&vh, g_vh);
    cudaGetSymbolAddress((void**)&vt, g_vt);
    cudaGetSymbolAddress((void**)&ph, g_p);
    cudaGetSymbolAddress((void**)&rv, g_r);

    const int SMEM = NSTG * STG;   // 98304
    static bool attr_set = false;
    if (!attr_set) {
        cudaFuncSetAttribute(gemm_big<0>, cudaFuncAttributeMaxDynamicSharedMemorySize, SMEM);
        cudaFuncSetAttribute(gemm_big<1>, cudaFuncAttributeMaxDynamicSharedMemorySize, SMEM);
        attr_set = true;
    }

    const float scale = 0.03608439182435161f;  // 1/sqrt(768)
    const dim3 thr(256);

    // QKV projections: [8192,768] @ [768,768] -> fp16
    const dim3 gQKV(DD / BN, (BB * NN) / BM, 1);
    gemm_qkv<<<gQKV, thr>>>(x, Wq, qh, BB * NN, DD, DD);
    gemm_qkv<<<gQKV, thr>>>(x, Wk, kh, BB * NN, DD, DD);
    gemm_qkv<<<gQKV, thr>>>(x, Wv, vh, BB * NN, DD, DD);

    // V^T per batch
    transpose_h<<<dim3(DD / 64, NN / 64, BB), thr>>>(vh, vt);

    // Probs (unnormalized): per batch [4096,4096] = exp(scale * Q @ K^T), fp16
    gemm_big<0><<<dim3(NN / BNb, NN / BMb, BB), thr, SMEM>>>(
        qh, kh, ph, nullptr, NN, DD,
        (size_t)NN * DD, (size_t)NN * DD, (size_t)NN * NN, scale);

    // 1 / rowsum
    rowsum_inv<<<BB * NN, thr>>>(ph, rv);

    // Output: per batch [4096,768] = diag(inv) * (P @ V),  V via V^T
    gemm_big<1><<<dim3(DD / BNb, NN / BMb, BB), thr, SMEM>>>(
        ph, vt, out, rv, DD, NN,
        (size_t)NN * NN, (size_t)NN * DD, (size_t)NN * DD, 1.f);
}

// round 8
// speedup vs baseline: 1.1834x; 1.1834x over previous
#include <cuda_runtime.h>
#include <cuda_fp16.h>
#include <cstdint>

#define BB 2
#define NN 4096
#define DD 768

constexpr int BM = 128, BN = 128, BK = 32;

// ---------------------------------------------------------------------------
// Scratch
// ---------------------------------------------------------------------------
__device__ __half g_qh[BB * NN * DD];
__device__ __half g_kh[BB * NN * DD];
__device__ __half g_vh[BB * NN * DD];
__device__ __half g_vt[BB * NN * DD];            // V^T per batch [DD, NN]
__device__ __half g_p[(size_t)BB * NN * NN];     // unnormalized exp(scores), fp16
__device__ float  g_r[BB * NN];                  // 1 / rowsum

// ---------------------------------------------------------------------------
// Helpers
// ---------------------------------------------------------------------------
__device__ __forceinline__ uint32_t smem_u32(const void* p) {
    uint32_t a;
    asm("{ .reg .u64 t; cvta.to.shared.u64 t, %1; cvt.u32.u64 %0, t; }" : "=r"(a) : "l"(p));
    return a;
}
__device__ __forceinline__ uint32_t sw64(uint32_t o) { return o ^ ((o >> 3) & 0x30); }

__device__ __forceinline__ void ldm_x4(uint32_t* r, uint32_t a) {
    asm volatile("ldmatrix.sync.aligned.m8n8.x4.shared.b16 {%0,%1,%2,%3}, [%4];"
                 : "=r"(r[0]), "=r"(r[1]), "=r"(r[2]), "=r"(r[3]) : "r"(a));
}
__device__ __forceinline__ void mma16816(float* c, const uint32_t* a, const uint32_t* b) {
    asm volatile(
        "mma.sync.aligned.m16n8k16.row.col.f32.f16.f16.f32 "
        "{%0,%1,%2,%3},{%4,%5,%6,%7},{%8,%9},{%0,%1,%2,%3};"
        : "+f"(c[0]), "+f"(c[1]), "+f"(c[2]), "+f"(c[3])
        : "r"(a[0]), "r"(a[1]), "r"(a[2]), "r"(a[3]), "r"(b[0]), "r"(b[1]));
}
__device__ __forceinline__ uint32_t h2u(__half2 h) { return *(uint32_t*)&h; }
__device__ __forceinline__ void cpa16(uint32_t dst, const void* src) {
    asm volatile("cp.async.cg.shared.global [%0], [%1], 16;" :: "r"(dst), "l"(src));
}

// ---------------------------------------------------------------------------
// Big GEMM (R6-proven mainloop): acc = A(fp16 [M,K]) @ B(fp16 [N,K])^T
//   MODE 0: C fp16 = exp(alpha * acc)       (unnormalized probs)
//   MODE 1: C fp32 = acc * inv[row]         (row-normalized PV output)
// 4-stage cp.async pipeline, CTA 128x128x32, 8 warps of 64x32, occ 2.
// ---------------------------------------------------------------------------
template <int MODE>
__global__ __launch_bounds__(256, 2)
void gemm_hh(const __half* __restrict__ Ag, const __half* __restrict__ Bg,
             void* __restrict__ Cgv, const float* __restrict__ inv,
             int Ncols, int K, size_t sAs, size_t sBs, size_t sCs, float alpha)
{
    extern __shared__ __align__(1024) __half sm[];
    __half* sA = sm;               // 4 stages x 4096 halfs
    __half* sB = sm + 4 * 4096;

    const int tid  = threadIdx.x;
    const int lane = tid & 31;
    const int warp = tid >> 5;
    const int wm = warp >> 2;      // 0..1 (64 rows)
    const int wn = warp & 3;       // 0..3 (32 cols)
    const int z = blockIdx.z;
    Ag += (size_t)z * sAs;
    Bg += (size_t)z * sBs;
    const int m0 = blockIdx.y * BM;
    const int n0 = blockIdx.x * BN;

    float acc[4][4][4];
#pragma unroll
    for (int mi = 0; mi < 4; mi++)
#pragma unroll
        for (int ni = 0; ni < 4; ni++)
#pragma unroll
            for (int r = 0; r < 4; r++) acc[mi][ni][r] = 0.f;

    auto LOAD = [&](int t) {
        const int s = t & 3;
        const int k0 = t * BK;
        const uint32_t da = smem_u32(sA + s * 4096);
        const uint32_t db = smem_u32(sB + s * 4096);
#pragma unroll
        for (int i = 0; i < 2; i++) {
            const int idx = tid + i * 256;
            const int r = idx >> 2, c = idx & 3;
            cpa16(da + sw64(r * 64 + c * 16), Ag + (size_t)(m0 + r) * K + k0 + c * 8);
            cpa16(db + sw64(r * 64 + c * 16), Bg + (size_t)(n0 + r) * K + k0 + c * 8);
        }
        asm volatile("cp.async.commit_group;" ::: "memory");
    };

    const int mrow  = wm * 64 + (lane & 15);
    const int acolb = (lane & 16);
    const int nrow  = wn * 32 + (lane & 7) + ((lane & 16) >> 1);
    const int bcolb = (lane & 8) << 1;

    auto KSTEP = [&](int s, int ks) {
        const uint32_t baseA = smem_u32(sA + s * 4096);
        const uint32_t baseB = smem_u32(sB + s * 4096);
        uint32_t a[4][4], b[2][4];
#pragma unroll
        for (int mi = 0; mi < 4; mi++)
            ldm_x4(a[mi], baseA + sw64((mrow + mi * 16) * 64 + ks * 2 + acolb));
#pragma unroll
        for (int n2 = 0; n2 < 2; n2++)
            ldm_x4(b[n2], baseB + sw64((nrow + n2 * 16) * 64 + ks * 2 + bcolb));
#pragma unroll
        for (int mi = 0; mi < 4; mi++)
#pragma unroll
            for (int ni = 0; ni < 4; ni++)
                mma16816(acc[mi][ni], a[mi], &b[ni >> 1][(ni & 1) * 2]);
    };

    const int NT = K / BK;
    LOAD(0); LOAD(1); LOAD(2);
    for (int t = 0; t < NT; t++) {
        asm volatile("cp.async.wait_group 2;" ::: "memory");
        __syncthreads();
        if (t + 3 < NT) LOAD(t + 3);
        else asm volatile("cp.async.commit_group;" ::: "memory");
        const int s = t & 3;
        KSTEP(s, 0);
        KSTEP(s, 16);
    }

    // ---- epilogue ----
    if (MODE == 0) {
        __half* C = (__half*)Cgv + (size_t)z * sCs;
#pragma unroll
        for (int mi = 0; mi < 4; mi++) {
            const int r = m0 + wm * 64 + mi * 16 + (lane >> 2);
#pragma unroll
            for (int ni = 0; ni < 4; ni++) {
                const int c = n0 + wn * 32 + ni * 8 + (lane & 3) * 2;
                *(__half2*)(C + (size_t)r * Ncols + c) =
                    __floats2half2_rn(__expf(alpha * acc[mi][ni][0]),
                                      __expf(alpha * acc[mi][ni][1]));
                *(__half2*)(C + (size_t)(r + 8) * Ncols + c) =
                    __floats2half2_rn(__expf(alpha * acc[mi][ni][2]),
                                      __expf(alpha * acc[mi][ni][3]));
            }
        }
    } else {
        float* C = (float*)Cgv + (size_t)z * sCs;
        const float* iv = inv + z * NN;
#pragma unroll
        for (int mi = 0; mi < 4; mi++) {
            const int r = m0 + wm * 64 + mi * 16 + (lane >> 2);
            const float s0 = iv[r], s1 = iv[r + 8];
#pragma unroll
            for (int ni = 0; ni < 4; ni++) {
                const int c = n0 + wn * 32 + ni * 8 + (lane & 3) * 2;
                *(float2*)(C + (size_t)r * Ncols + c) =
                    make_float2(s0 * acc[mi][ni][0], s0 * acc[mi][ni][1]);
                *(float2*)(C + (size_t)(r + 8) * Ncols + c) =
                    make_float2(s1 * acc[mi][ni][2], s1 * acc[mi][ni][3]);
            }
        }
    }
}

// ---------------------------------------------------------------------------
// QKV projection GEMM: C(fp16) = A(fp32 [M,K]) @ B(fp32 [K,N])   (R6-proven)
// ---------------------------------------------------------------------------
__global__ __launch_bounds__(256, 2)
void gemm_qkv(const float* __restrict__ Ag, const float* __restrict__ Bg,
              __half* __restrict__ Cg, int M, int Ncols, int K)
{
    __shared__ __align__(1024) __half sA[2][BM * BK];
    __shared__ __align__(1024) __half sB[2][BN * BK];

    const int tid  = threadIdx.x;
    const int lane = tid & 31;
    const int warp = tid >> 5;
    const int wm = warp >> 2;
    const int wn = warp & 3;
    const int m0 = blockIdx.y * BM;
    const int n0 = blockIdx.x * BN;

    float acc[4][4][4];
#pragma unroll
    for (int mi = 0; mi < 4; mi++)
#pragma unroll
        for (int ni = 0; ni < 4; ni++)
#pragma unroll
            for (int r = 0; r < 4; r++) acc[mi][ni][r] = 0.f;

    float4 fa[4];
    float  fbn[16];
    const int nnf = tid & 127;
    const int q0  = tid >> 7;

    auto LDGA = [&](int t) {
        const int k0 = t * BK;
#pragma unroll
        for (int i = 0; i < 4; i++) {
            const int f = tid + i * 256;
            fa[i] = *(const float4*)(Ag + (size_t)(m0 + (f >> 3)) * K + k0 + (f & 7) * 4);
        }
    };
    auto STSA = [&](int s) {
#pragma unroll
        for (int i = 0; i < 4; i++) {
            const int f = tid + i * 256;
            uint2 u;
            u.x = h2u(__floats2half2_rn(fa[i].x, fa[i].y));
            u.y = h2u(__floats2half2_rn(fa[i].z, fa[i].w));
            *(uint2*)((char*)sA[s] + sw64((f >> 3) * 64 + (f & 7) * 8)) = u;
        }
    };
    auto LDGB = [&](int t) {
        const int k0 = t * BK;
#pragma unroll
        for (int i = 0; i < 4; i++) {
            const int q = q0 + 2 * i;
            const float* src = Bg + (size_t)(k0 + q * 4) * Ncols + n0 + nnf;
            fbn[i * 4 + 0] = src[0];
            fbn[i * 4 + 1] = src[Ncols];
            fbn[i * 4 + 2] = src[2 * Ncols];
            fbn[i * 4 + 3] = src[3 * Ncols];
        }
    };
    auto STSB = [&](int s) {
#pragma unroll
        for (int i = 0; i < 4; i++) {
            const int q = q0 + 2 * i;
            uint2 u;
            u.x = h2u(__floats2half2_rn(fbn[i * 4 + 0], fbn[i * 4 + 1]));
            u.y = h2u(__floats2half2_rn(fbn[i * 4 + 2], fbn[i * 4 + 3]));
            *(uint2*)((char*)sB[s] + sw64(nnf * 64 + q * 8)) = u;
        }
    };

    const int mrow  = wm * 64 + (lane & 15);
    const int acolb = (lane & 16);
    const int nrow  = wn * 32 + (lane & 7) + ((lane & 16) >> 1);
    const int bcolb = (lane & 8) << 1;

    auto KSTEP = [&](int s, int ks) {
        const uint32_t baseA = smem_u32(sA[s]);
        const uint32_t baseB = smem_u32(sB[s]);
        uint32_t a[4][4], b[2][4];
#pragma unroll
        for (int mi = 0; mi < 4; mi++)
            ldm_x4(a[mi], baseA + sw64((mrow + mi * 16) * 64 + ks * 2 + acolb));
#pragma unroll
        for (int n2 = 0; n2 < 2; n2++)
            ldm_x4(b[n2], baseB + sw64((nrow + n2 * 16) * 64 + ks * 2 + bcolb));
#pragma unroll
        for (int mi = 0; mi < 4; mi++)
#pragma unroll
            for (int ni = 0; ni < 4; ni++)
                mma16816(acc[mi][ni], a[mi], &b[ni >> 1][(ni & 1) * 2]);
    };

    LDGA(0); LDGB(0);
    STSA(0); STSB(0);
    __syncthreads();

    const int NT = K / BK;
    for (int t = 0; t < NT; t++) {
        const int s = t & 1;
        const bool more = (t + 1 < NT);
        if (more) LDGA(t + 1);
        KSTEP(s, 0);
        if (more) { STSA(s ^ 1); LDGB(t + 1); }
        KSTEP(s, 16);
        if (more) STSB(s ^ 1);
        __syncthreads();
    }

#pragma unroll
    for (int mi = 0; mi < 4; mi++) {
        const int r = m0 + wm * 64 + mi * 16 + (lane >> 2);
#pragma unroll
        for (int ni = 0; ni < 4; ni++) {
            const int c = n0 + wn * 32 + ni * 8 + (lane & 3) * 2;
            *(__half2*)(Cg + (size_t)r * Ncols + c) =
                __floats2half2_rn(acc[mi][ni][0], acc[mi][ni][1]);
            *(__half2*)(Cg + (size_t)(r + 8) * Ncols + c) =
                __floats2half2_rn(acc[mi][ni][2], acc[mi][ni][3]);
        }
    }
}

// ---------------------------------------------------------------------------
// fp16 transpose per batch: src [NN, DD] -> dst [DD, NN]
// ---------------------------------------------------------------------------
__global__ __launch_bounds__(256)
void transpose_h(const __half* __restrict__ src, __half* __restrict__ dst)
{
    __shared__ __half tile[64][65];
    const int z = blockIdx.z;
    src += (size_t)z * NN * DD;
    dst += (size_t)z * NN * DD;
    const int d0 = blockIdx.x * 64;
    const int t0 = blockIdx.y * 64;
    const int tid = threadIdx.x;

#pragma unroll
    for (int i = 0; i < 8; i++) {
        const int idx = tid + i * 256;
        const int r = idx >> 5, c2 = idx & 31;
        __half2 v = *(const __half2*)(src + (size_t)(t0 + r) * DD + d0 + c2 * 2);
        tile[r][c2 * 2]     = __low2half(v);
        tile[r][c2 * 2 + 1] = __high2half(v);
    }
    __syncthreads();
#pragma unroll
    for (int i = 0; i < 8; i++) {
        const int idx = tid + i * 256;
        const int dr = idx >> 5, c2 = idx & 31;
        __half2 v = __halves2half2(tile[c2 * 2][dr], tile[c2 * 2 + 1][dr]);
        *(__half2*)(dst + (size_t)(d0 + dr) * NN + t0 + c2 * 2) = v;
    }
}

// ---------------------------------------------------------------------------
// Row sums of fp16 probs -> 1/sum (fp32). One block per row of 4096.
// ---------------------------------------------------------------------------
__global__ __launch_bounds__(256)
void rowsum_inv(const __half* __restrict__ P, float* __restrict__ inv)
{
    const __half2* p = (const __half2*)(P + (size_t)blockIdx.x * NN);
    const int t = threadIdx.x;

    float s = 0.f;
#pragma unroll
    for (int i = 0; i < 8; i++) {
        const float2 f = __half22float2(p[t + i * 256]);
        s += f.x + f.y;
    }
    __shared__ float sh[8];
#pragma unroll
    for (int o = 16; o; o >>= 1) s += __shfl_xor_sync(0xffffffffu, s, o);
    if ((t & 31) == 0) sh[t >> 5] = s;
    __syncthreads();
    if (t == 0) {
        float tot = 0.f;
#pragma unroll
        for (int i = 0; i < 8; i++) tot += sh[i];
        inv[blockIdx.x] = 1.0f / tot;
    }
}

// ---------------------------------------------------------------------------
extern "C" void kernel_launch(void* const* d_in, const int* in_sizes, int n_in,
                              void* d_out, int out_size)
{
    const float* x  = (const float*)d_in[0];
    const float* Wq = (const float*)d_in[1];
    const float* Wk = (const float*)d_in[2];
    const float* Wv = (const float*)d_in[3];
    float* out = (float*)d_out;

    __half *qh, *kh, *vh, *vt, *ph;
    float* rv;
    cudaGetSymbolAddress((void**)&qh, g_qh);
    cudaGetSymbolAddress((void**)&kh, g_kh);
    cudaGetSymbolAddress((void**)&vh, g_vh);
    cudaGetSymbolAddress((void**)&vt, g_vt);
    cudaGetSymbolAddress((void**)&ph, g_p);
    cudaGetSymbolAddress((void**)&rv, g_r);

    const int SMEM = 4 * 2 * BM * BK * 2;   // 65536
    static bool attr_set = false;
    if (!attr_set) {
        cudaFuncSetAttribute(gemm_hh<0>, cudaFuncAttributeMaxDynamicSharedMemorySize, SMEM);
        cudaFuncSetAttribute(gemm_hh<1>, cudaFuncAttributeMaxDynamicSharedMemorySize, SMEM);
        attr_set = true;
    }

    const float scale = 0.03608439182435161f;  // 1/sqrt(768)
    const dim3 thr(256);

    // QKV projections: [8192,768] @ [768,768] -> fp16
    const dim3 gQKV(DD / BN, (BB * NN) / BM, 1);
    gemm_qkv<<<gQKV, thr>>>(x, Wq, qh, BB * NN, DD, DD);
    gemm_qkv<<<gQKV, thr>>>(x, Wk, kh, BB * NN, DD, DD);
    gemm_qkv<<<gQKV, thr>>>(x, Wv, vh, BB * NN, DD, DD);

    // V^T per batch
    transpose_h<<<dim3(DD / 64, NN / 64, BB), thr>>>(vh, vt);

    // Probs (unnormalized): per batch [4096,4096] = exp(scale * Q @ K^T), fp16
    gemm_hh<0><<<dim3(NN / BN, NN / BM, BB), thr, SMEM>>>(
        qh, kh, ph, nullptr, NN, DD,
        (size_t)NN * DD, (size_t)NN * DD, (size_t)NN * NN, scale);

    // 1 / rowsum
    rowsum_inv<<<BB * NN, thr>>>(ph, rv);

    // Output: per batch [4096,768] = diag(inv) * (P @ V),  V via V^T
    gemm_hh<1><<<dim3(DD / BN, NN / BM, BB), thr, SMEM>>>(
        ph, vt, out, rv, DD, NN,
        (size_t)NN * NN, (size_t)NN * DD, (size_t)NN * DD, 1.f);
}

// round 9
// speedup vs baseline: 1.2489x; 1.0553x over previous
#include <cuda_runtime.h>
#include <cuda_fp16.h>
#include <cstdint>

#define BB 2
#define NN 4096
#define DD 768

// QKV tiling (proven): CTA 128x128x32
constexpr int BM = 128, BN = 128, BK = 32;
// big GEMM: CTA 128x128x64, 3-stage
constexpr int BKb   = 64;
constexpr int STG_A = BM * BKb * 2;        // 16384 B
constexpr int STG   = 2 * STG_A;           // 32768 B (A+B)
constexpr int NSTG  = 3;                   // 98304 B total

// ---------------------------------------------------------------------------
// Scratch
// ---------------------------------------------------------------------------
__device__ __half g_qh[BB * NN * DD];
__device__ __half g_kh[BB * NN * DD];
__device__ __half g_vh[BB * NN * DD];
__device__ __half g_vt[BB * NN * DD];            // V^T per batch [DD, NN]
__device__ __half g_p[(size_t)BB * NN * NN];     // unnormalized exp(scores), fp16
__device__ float  g_r[BB * NN];                  // 1 / rowsum

// ---------------------------------------------------------------------------
// Helpers
// ---------------------------------------------------------------------------
__device__ __forceinline__ uint32_t smem_u32(const void* p) {
    uint32_t a;
    asm("{ .reg .u64 t; cvta.to.shared.u64 t, %1; cvt.u32.u64 %0, t; }" : "=r"(a) : "l"(p));
    return a;
}
__device__ __forceinline__ uint32_t sw64(uint32_t o)  { return o ^ ((o >> 3) & 0x30); }
__device__ __forceinline__ uint32_t sw128(uint32_t o) { return o ^ ((o >> 3) & 0x70); }

__device__ __forceinline__ void ldm_x4(uint32_t* r, uint32_t a) {
    asm volatile("ldmatrix.sync.aligned.m8n8.x4.shared.b16 {%0,%1,%2,%3}, [%4];"
                 : "=r"(r[0]), "=r"(r[1]), "=r"(r[2]), "=r"(r[3]) : "r"(a));
}
__device__ __forceinline__ void mma16816(float* c, const uint32_t* a, const uint32_t* b) {
    asm volatile(
        "mma.sync.aligned.m16n8k16.row.col.f32.f16.f16.f32 "
        "{%0,%1,%2,%3},{%4,%5,%6,%7},{%8,%9},{%0,%1,%2,%3};"
        : "+f"(c[0]), "+f"(c[1]), "+f"(c[2]), "+f"(c[3])
        : "r"(a[0]), "r"(a[1]), "r"(a[2]), "r"(a[3]), "r"(b[0]), "r"(b[1]));
}
__device__ __forceinline__ uint32_t h2u(__half2 h) { return *(uint32_t*)&h; }
__device__ __forceinline__ void cpa16(uint32_t dst, const void* src) {
    asm volatile("cp.async.cg.shared.global [%0], [%1], 16;" :: "r"(dst), "l"(src));
}

// ---------------------------------------------------------------------------
// Big GEMM: acc = A(fp16 [M,K]) @ B(fp16 [N,K])^T
//   MODE 0: C fp16 = exp(alpha * acc)       (unnormalized probs)
//   MODE 1: C fp32 = acc * inv[row]         (row-normalized PV output)
// CTA 128x128x64, 3-stage cp.async (128B SW128 rows), 8 warps of 64x32, occ 2.
// ---------------------------------------------------------------------------
template <int MODE>
__global__ __launch_bounds__(256, 2)
void gemm_hh(const __half* __restrict__ Ag, const __half* __restrict__ Bg,
             void* __restrict__ Cgv, const float* __restrict__ inv,
             int Ncols, int K, size_t sAs, size_t sBs, size_t sCs, float alpha)
{
    extern __shared__ __align__(1024) char sm[];

    const int tid  = threadIdx.x;
    const int lane = tid & 31;
    const int warp = tid >> 5;
    const int wm = warp >> 2;      // 0..1 (64 rows)
    const int wn = warp & 3;       // 0..3 (32 cols)
    const int z = blockIdx.z;
    Ag += (size_t)z * sAs;
    Bg += (size_t)z * sBs;
    const int m0 = blockIdx.y * BM;
    const int n0 = blockIdx.x * BN;

    float acc[4][4][4];
#pragma unroll
    for (int mi = 0; mi < 4; mi++)
#pragma unroll
        for (int ni = 0; ni < 4; ni++)
#pragma unroll
            for (int r = 0; r < 4; r++) acc[mi][ni][r] = 0.f;

    // stage layout: [A: 128 rows x 128B][B: 128 rows x 128B]
    auto LOAD = [&](int t, int s) {
        const int k0 = t * BKb;
        const uint32_t da = smem_u32(sm + s * STG);
        const uint32_t db = da + STG_A;
        // 1024 chunks each for A and B; 4 per thread each
#pragma unroll
        for (int i = 0; i < 4; i++) {
            const int idx = tid + i * 256;
            const int r = idx >> 3, c = idx & 7;
            cpa16(da + sw128(r * 128 + c * 16), Ag + (size_t)(m0 + r) * K + k0 + c * 8);
            cpa16(db + sw128(r * 128 + c * 16), Bg + (size_t)(n0 + r) * K + k0 + c * 8);
        }
        asm volatile("cp.async.commit_group;" ::: "memory");
    };

    const int mrow  = wm * 64 + (lane & 15);
    const int acolb = (lane & 16);                 // +16B for k upper 8
    const int nrow  = wn * 32 + (lane & 7) + ((lane & 16) >> 1);
    const int bcolb = (lane & 8) << 1;

    auto KSTEP = [&](int s, int ks) {
        const uint32_t baseA = smem_u32(sm + s * STG);
        const uint32_t baseB = baseA + STG_A;
        uint32_t a[4][4], b[2][4];
#pragma unroll
        for (int mi = 0; mi < 4; mi++)
            ldm_x4(a[mi], baseA + sw128((mrow + mi * 16) * 128 + ks * 2 + acolb));
#pragma unroll
        for (int n2 = 0; n2 < 2; n2++)
            ldm_x4(b[n2], baseB + sw128((nrow + n2 * 16) * 128 + ks * 2 + bcolb));
#pragma unroll
        for (int mi = 0; mi < 4; mi++)
#pragma unroll
            for (int ni = 0; ni < 4; ni++)
                mma16816(acc[mi][ni], a[mi], &b[ni >> 1][(ni & 1) * 2]);
    };

    const int NT = K / BKb;     // 12 (score) or 64 (pv)
    LOAD(0, 0); LOAD(1, 1);
    int s = 0;
    for (int t = 0; t < NT; t++) {
        asm volatile("cp.async.wait_group 1;" ::: "memory");
        __syncthreads();
        const int sn = (s + 2 >= NSTG) ? s + 2 - NSTG : s + 2;
        if (t + 2 < NT) LOAD(t + 2, sn);
        else asm volatile("cp.async.commit_group;" ::: "memory");
        KSTEP(s, 0);
        KSTEP(s, 16);
        KSTEP(s, 32);
        KSTEP(s, 48);
        s = (s + 1 >= NSTG) ? 0 : s + 1;
    }

    // ---- epilogue ----
    if (MODE == 0) {
        __half* C = (__half*)Cgv + (size_t)z * sCs;
#pragma unroll
        for (int mi = 0; mi < 4; mi++) {
            const int r = m0 + wm * 64 + mi * 16 + (lane >> 2);
#pragma unroll
            for (int ni = 0; ni < 4; ni++) {
                const int c = n0 + wn * 32 + ni * 8 + (lane & 3) * 2;
                *(__half2*)(C + (size_t)r * Ncols + c) =
                    __floats2half2_rn(__expf(alpha * acc[mi][ni][0]),
                                      __expf(alpha * acc[mi][ni][1]));
                *(__half2*)(C + (size_t)(r + 8) * Ncols + c) =
                    __floats2half2_rn(__expf(alpha * acc[mi][ni][2]),
                                      __expf(alpha * acc[mi][ni][3]));
            }
        }
    } else {
        float* C = (float*)Cgv + (size_t)z * sCs;
        const float* iv = inv + z * NN;
#pragma unroll
        for (int mi = 0; mi < 4; mi++) {
            const int r = m0 + wm * 64 + mi * 16 + (lane >> 2);
            const float s0 = iv[r], s1 = iv[r + 8];
#pragma unroll
            for (int ni = 0; ni < 4; ni++) {
                const int c = n0 + wn * 32 + ni * 8 + (lane & 3) * 2;
                *(float2*)(C + (size_t)r * Ncols + c) =
                    make_float2(s0 * acc[mi][ni][0], s0 * acc[mi][ni][1]);
                *(float2*)(C + (size_t)(r + 8) * Ncols + c) =
                    make_float2(s1 * acc[mi][ni][2], s1 * acc[mi][ni][3]);
            }
        }
    }
}

// ---------------------------------------------------------------------------
// QKV projection GEMM: C(fp16) = A(fp32 [M,K]) @ B(fp32 [K,N])   (R6-proven)
// ---------------------------------------------------------------------------
__global__ __launch_bounds__(256, 2)
void gemm_qkv(const float* __restrict__ Ag, const float* __restrict__ Bg,
              __half* __restrict__ Cg, int M, int Ncols, int K)
{
    __shared__ __align__(1024) __half sA[2][BM * BK];
    __shared__ __align__(1024) __half sB[2][BN * BK];

    const int tid  = threadIdx.x;
    const int lane = tid & 31;
    const int warp = tid >> 5;
    const int wm = warp >> 2;
    const int wn = warp & 3;
    const int m0 = blockIdx.y * BM;
    const int n0 = blockIdx.x * BN;

    float acc[4][4][4];
#pragma unroll
    for (int mi = 0; mi < 4; mi++)
#pragma unroll
        for (int ni = 0; ni < 4; ni++)
#pragma unroll
            for (int r = 0; r < 4; r++) acc[mi][ni][r] = 0.f;

    float4 fa[4];
    float  fbn[16];
    const int nnf = tid & 127;
    const int q0  = tid >> 7;

    auto LDGA = [&](int t) {
        const int k0 = t * BK;
#pragma unroll
        for (int i = 0; i < 4; i++) {
            const int f = tid + i * 256;
            fa[i] = *(const float4*)(Ag + (size_t)(m0 + (f >> 3)) * K + k0 + (f & 7) * 4);
        }
    };
    auto STSA = [&](int s) {
#pragma unroll
        for (int i = 0; i < 4; i++) {
            const int f = tid + i * 256;
            uint2 u;
            u.x = h2u(__floats2half2_rn(fa[i].x, fa[i].y));
            u.y = h2u(__floats2half2_rn(fa[i].z, fa[i].w));
            *(uint2*)((char*)sA[s] + sw64((f >> 3) * 64 + (f & 7) * 8)) = u;
        }
    };
    auto LDGB = [&](int t) {
        const int k0 = t * BK;
#pragma unroll
        for (int i = 0; i < 4; i++) {
            const int q = q0 + 2 * i;
            const float* src = Bg + (size_t)(k0 + q * 4) * Ncols + n0 + nnf;
            fbn[i * 4 + 0] = src[0];
            fbn[i * 4 + 1] = src[Ncols];
            fbn[i * 4 + 2] = src[2 * Ncols];
            fbn[i * 4 + 3] = src[3 * Ncols];
        }
    };
    auto STSB = [&](int s) {
#pragma unroll
        for (int i = 0; i < 4; i++) {
            const int q = q0 + 2 * i;
            uint2 u;
            u.x = h2u(__floats2half2_rn(fbn[i * 4 + 0], fbn[i * 4 + 1]));
            u.y = h2u(__floats2half2_rn(fbn[i * 4 + 2], fbn[i * 4 + 3]));
            *(uint2*)((char*)sB[s] + sw64(nnf * 64 + q * 8)) = u;
        }
    };

    const int mrow  = wm * 64 + (lane & 15);
    const int acolb = (lane & 16);
    const int nrow  = wn * 32 + (lane & 7) + ((lane & 16) >> 1);
    const int bcolb = (lane & 8) << 1;

    auto KSTEP = [&](int s, int ks) {
        const uint32_t baseA = smem_u32(sA[s]);
        const uint32_t baseB = smem_u32(sB[s]);
        uint32_t a[4][4], b[2][4];
#pragma unroll
        for (int mi = 0; mi < 4; mi++)
            ldm_x4(a[mi], baseA + sw64((mrow + mi * 16) * 64 + ks * 2 + acolb));
#pragma unroll
        for (int n2 = 0; n2 < 2; n2++)
            ldm_x4(b[n2], baseB + sw64((nrow + n2 * 16) * 64 + ks * 2 + bcolb));
#pragma unroll
        for (int mi = 0; mi < 4; mi++)
#pragma unroll
            for (int ni = 0; ni < 4; ni++)
                mma16816(acc[mi][ni], a[mi], &b[ni >> 1][(ni & 1) * 2]);
    };

    LDGA(0); LDGB(0);
    STSA(0); STSB(0);
    __syncthreads();

    const int NT = K / BK;
    for (int t = 0; t < NT; t++) {
        const int s = t & 1;
        const bool more = (t + 1 < NT);
        if (more) LDGA(t + 1);
        KSTEP(s, 0);
        if (more) { STSA(s ^ 1); LDGB(t + 1); }
        KSTEP(s, 16);
        if (more) STSB(s ^ 1);
        __syncthreads();
    }

#pragma unroll
    for (int mi = 0; mi < 4; mi++) {
        const int r = m0 + wm * 64 + mi * 16 + (lane >> 2);
#pragma unroll
        for (int ni = 0; ni < 4; ni++) {
            const int c = n0 + wn * 32 + ni * 8 + (lane & 3) * 2;
            *(__half2*)(Cg + (size_t)r * Ncols + c) =
                __floats2half2_rn(acc[mi][ni][0], acc[mi][ni][1]);
            *(__half2*)(Cg + (size_t)(r + 8) * Ncols + c) =
                __floats2half2_rn(acc[mi][ni][2], acc[mi][ni][3]);
        }
    }
}

// ---------------------------------------------------------------------------
// fp16 transpose per batch: src [NN, DD] -> dst [DD, NN]
// ---------------------------------------------------------------------------
__global__ __launch_bounds__(256)
void transpose_h(const __half* __restrict__ src, __half* __restrict__ dst)
{
    __shared__ __half tile[64][65];
    const int z = blockIdx.z;
    src += (size_t)z * NN * DD;
    dst += (size_t)z * NN * DD;
    const int d0 = blockIdx.x * 64;
    const int t0 = blockIdx.y * 64;
    const int tid = threadIdx.x;

#pragma unroll
    for (int i = 0; i < 8; i++) {
        const int idx = tid + i * 256;
        const int r = idx >> 5, c2 = idx & 31;
        __half2 v = *(const __half2*)(src + (size_t)(t0 + r) * DD + d0 + c2 * 2);
        tile[r][c2 * 2]     = __low2half(v);
        tile[r][c2 * 2 + 1] = __high2half(v);
    }
    __syncthreads();
#pragma unroll
    for (int i = 0; i < 8; i++) {
        const int idx = tid + i * 256;
        const int dr = idx >> 5, c2 = idx & 31;
        __half2 v = __halves2half2(tile[c2 * 2][dr], tile[c2 * 2 + 1][dr]);
        *(__half2*)(dst + (size_t)(d0 + dr) * NN + t0 + c2 * 2) = v;
    }
}

// ---------------------------------------------------------------------------
// Row sums of fp16 probs -> 1/sum (fp32). One block per row of 4096.
// ---------------------------------------------------------------------------
__global__ __launch_bounds__(256)
void rowsum_inv(const __half* __restrict__ P, float* __restrict__ inv)
{
    const __half2* p = (const __half2*)(P + (size_t)blockIdx.x * NN);
    const int t = threadIdx.x;

    float s = 0.f;
#pragma unroll
    for (int i = 0; i < 8; i++) {
        const float2 f = __half22float2(p[t + i * 256]);
        s += f.x + f.y;
    }
    __shared__ float sh[8];
#pragma unroll
    for (int o = 16; o; o >>= 1) s += __shfl_xor_sync(0xffffffffu, s, o);
    if ((t & 31) == 0) sh[t >> 5] = s;
    __syncthreads();
    if (t == 0) {
        float tot = 0.f;
#pragma unroll
        for (int i = 0; i < 8; i++) tot += sh[i];
        inv[blockIdx.x] = 1.0f / tot;
    }
}

// ---------------------------------------------------------------------------
extern "C" void kernel_launch(void* const* d_in, const int* in_sizes, int n_in,
                              void* d_out, int out_size)
{
    const float* x  = (const float*)d_in[0];
    const float* Wq = (const float*)d_in[1];
    const float* Wk = (const float*)d_in[2];
    const float* Wv = (const float*)d_in[3];
    float* out = (float*)d_out;

    __half *qh, *kh, *vh, *vt, *ph;
    float* rv;
    cudaGetSymbolAddress((void**)&qh, g_qh);
    cudaGetSymbolAddress((void**)&kh, g_kh);
    cudaGetSymbolAddress((void**)&vh, g_vh);
    cudaGetSymbolAddress((void**)&vt, g_vt);
    cudaGetSymbolAddress((void**)&ph, g_p);
    cudaGetSymbolAddress((void**)&rv, g_r);

    const int SMEM = NSTG * STG;   // 98304
    static bool attr_set = false;
    if (!attr_set) {
        cudaFuncSetAttribute(gemm_hh<0>, cudaFuncAttributeMaxDynamicSharedMemorySize, SMEM);
        cudaFuncSetAttribute(gemm_hh<1>, cudaFuncAttributeMaxDynamicSharedMemorySize, SMEM);
        attr_set = true;
    }

    const float scale = 0.03608439182435161f;  // 1/sqrt(768)
    const dim3 thr(256);

    // QKV projections: [8192,768] @ [768,768] -> fp16
    const dim3 gQKV(DD / BN, (BB * NN) / BM, 1);
    gemm_qkv<<<gQKV, thr>>>(x, Wq, qh, BB * NN, DD, DD);
    gemm_qkv<<<gQKV, thr>>>(x, Wk, kh, BB * NN, DD, DD);
    gemm_qkv<<<gQKV, thr>>>(x, Wv, vh, BB * NN, DD, DD);

    // V^T per batch
    transpose_h<<<dim3(DD / 64, NN / 64, BB), thr>>>(vh, vt);

    // Probs (unnormalized): per batch [4096,4096] = exp(scale * Q @ K^T), fp16
    gemm_hh<0><<<dim3(NN / BN, NN / BM, BB), thr, SMEM>>>(
        qh, kh, ph, nullptr, NN, DD,
        (size_t)NN * DD, (size_t)NN * DD, (size_t)NN * NN, scale);

    // 1 / rowsum
    rowsum_inv<<<BB * NN, thr>>>(ph, rv);

    // Output: per batch [4096,768] = diag(inv) * (P @ V),  V via V^T
    gemm_hh<1><<<dim3(DD / BN, NN / BM, BB), thr, SMEM>>>(
        ph, vt, out, rv, DD, NN,
        (size_t)NN * NN, (size_t)NN * DD, (size_t)NN * DD, 1.f);
}

// round 10
// speedup vs baseline: 1.5790x; 1.2643x over previous
#include <cuda_runtime.h>
#include <cuda_fp16.h>
#include <cstdint>

#define BB 2
#define NN 4096
#define DD 768

constexpr int BM = 128, BN = 128;
constexpr int BKb   = 64;
constexpr int STG_A = BM * BKb * 2;        // 16384 B
constexpr int STG   = 2 * STG_A;           // 32768 B
constexpr int NSTG  = 3;                   // 98304 B

// ---------------------------------------------------------------------------
// Scratch
// ---------------------------------------------------------------------------
__device__ __half g_xh[BB * NN * DD];            // x in fp16
__device__ __half g_wc[3 * DD * DD];             // [Wq^T;Wk^T;Wv^T] fp16, [2304,768] K-major
__device__ __half g_qh[BB * NN * DD];
__device__ __half g_kh[BB * NN * DD];
__device__ __half g_vh[BB * NN * DD];
__device__ __half g_vt[BB * NN * DD];            // V^T per batch [DD, NN]
__device__ __half g_p[(size_t)BB * NN * NN];     // unnormalized exp(scores), fp16
__device__ float  g_r[BB * NN];                  // row sums (atomics)

// ---------------------------------------------------------------------------
// Helpers
// ---------------------------------------------------------------------------
__device__ __forceinline__ uint32_t smem_u32(const void* p) {
    uint32_t a;
    asm("{ .reg .u64 t; cvta.to.shared.u64 t, %1; cvt.u32.u64 %0, t; }" : "=r"(a) : "l"(p));
    return a;
}
__device__ __forceinline__ uint32_t sw128(uint32_t o) { return o ^ ((o >> 3) & 0x70); }

__device__ __forceinline__ void ldm_x4(uint32_t* r, uint32_t a) {
    asm volatile("ldmatrix.sync.aligned.m8n8.x4.shared.b16 {%0,%1,%2,%3}, [%4];"
                 : "=r"(r[0]), "=r"(r[1]), "=r"(r[2]), "=r"(r[3]) : "r"(a));
}
__device__ __forceinline__ void mma16816(float* c, const uint32_t* a, const uint32_t* b) {
    asm volatile(
        "mma.sync.aligned.m16n8k16.row.col.f32.f16.f16.f32 "
        "{%0,%1,%2,%3},{%4,%5,%6,%7},{%8,%9},{%0,%1,%2,%3};"
        : "+f"(c[0]), "+f"(c[1]), "+f"(c[2]), "+f"(c[3])
        : "r"(a[0]), "r"(a[1]), "r"(a[2]), "r"(a[3]), "r"(b[0]), "r"(b[1]));
}
__device__ __forceinline__ uint32_t h2u(__half2 h) { return *(uint32_t*)&h; }
__device__ __forceinline__ void cpa16(uint32_t dst, const void* src) {
    asm volatile("cp.async.cg.shared.global [%0], [%1], 16;" :: "r"(dst), "l"(src));
}

// ===========================================================================
// Shared mainloop pieces (BK=64, 3-stage cp.async, CTA 128x128, warps 64x32)
// ===========================================================================
struct Frag { float acc[4][4][4]; };

#define MAINLOOP_BODY(Ag, Bg, K)                                               \
    float acc[4][4][4];                                                        \
    _Pragma("unroll") for (int mi = 0; mi < 4; mi++)                           \
    _Pragma("unroll") for (int ni = 0; ni < 4; ni++)                           \
    _Pragma("unroll") for (int r = 0; r < 4; r++) acc[mi][ni][r] = 0.f;        \
    auto LOAD = [&](int t, int st) {                                           \
        const int k0 = t * BKb;                                                \
        const uint32_t da = smem_u32(sm + st * STG);                           \
        const uint32_t db = da + STG_A;                                        \
        _Pragma("unroll") for (int i = 0; i < 4; i++) {                        \
            const int idx = tid + i * 256;                                     \
            const int r = idx >> 3, c = idx & 7;                               \
            cpa16(da + sw128(r * 128 + c * 16), Ag + (size_t)(m0 + r) * K + k0 + c * 8); \
            cpa16(db + sw128(r * 128 + c * 16), Bg + (size_t)(n0 + r) * K + k0 + c * 8); \
        }                                                                      \
        asm volatile("cp.async.commit_group;" ::: "memory");                   \
    };                                                                         \
    const int mrow  = wm * 64 + (lane & 15);                                   \
    const int acolb = (lane & 16);                                             \
    const int nrow  = wn * 32 + (lane & 7) + ((lane & 16) >> 1);               \
    const int bcolb = (lane & 8) << 1;                                         \
    auto KSTEP = [&](int st, int ks) {                                         \
        const uint32_t baseA = smem_u32(sm + st * STG);                        \
        const uint32_t baseB = baseA + STG_A;                                  \
        uint32_t a[4][4], b[2][4];                                             \
        _Pragma("unroll") for (int mi = 0; mi < 4; mi++)                       \
            ldm_x4(a[mi], baseA + sw128((mrow + mi * 16) * 128 + ks * 2 + acolb)); \
        _Pragma("unroll") for (int n2 = 0; n2 < 2; n2++)                       \
            ldm_x4(b[n2], baseB + sw128((nrow + n2 * 16) * 128 + ks * 2 + bcolb)); \
        _Pragma("unroll") for (int mi = 0; mi < 4; mi++)                       \
        _Pragma("unroll") for (int ni = 0; ni < 4; ni++)                       \
            mma16816(acc[mi][ni], a[mi], &b[ni >> 1][(ni & 1) * 2]);           \
    };                                                                         \
    const int NT = (K) / BKb;                                                  \
    LOAD(0, 0); LOAD(1, 1);                                                    \
    int st = 0;                                                                \
    for (int t = 0; t < NT; t++) {                                             \
        asm volatile("cp.async.wait_group 1;" ::: "memory");                   \
        __syncthreads();                                                       \
        const int sn = (st + 2 >= NSTG) ? st + 2 - NSTG : st + 2;              \
        if (t + 2 < NT) LOAD(t + 2, sn);                                       \
        else asm volatile("cp.async.commit_group;" ::: "memory");              \
        KSTEP(st, 0); KSTEP(st, 16); KSTEP(st, 32); KSTEP(st, 48);             \
        st = (st + 1 >= NSTG) ? 0 : st + 1;                                    \
    }

// ---------------------------------------------------------------------------
// Score GEMM: P = exp(scale * Q @ K^T) fp16, with fused row-sum atomics
// ---------------------------------------------------------------------------
__global__ __launch_bounds__(256, 2)
void gemm_score(const __half* __restrict__ Qg, const __half* __restrict__ Kg,
                __half* __restrict__ Pg, float* __restrict__ rsum, float alpha)
{
    extern __shared__ __align__(1024) char sm[];
    const int tid  = threadIdx.x;
    const int lane = tid & 31;
    const int warp = tid >> 5;
    const int wm = warp >> 2, wn = warp & 3;
    const int z = blockIdx.z;
    const __half* Ag = Qg + (size_t)z * NN * DD;
    const __half* Bg = Kg + (size_t)z * NN * DD;
    const int m0 = blockIdx.y * BM;
    const int n0 = blockIdx.x * BN;

    MAINLOOP_BODY(Ag, Bg, DD)

    __half* C = Pg + (size_t)z * NN * NN;
    float* rs = rsum + z * NN;
#pragma unroll
    for (int mi = 0; mi < 4; mi++) {
        const int r = m0 + wm * 64 + mi * 16 + (lane >> 2);
        float s0 = 0.f, s1 = 0.f;
#pragma unroll
        for (int ni = 0; ni < 4; ni++) {
            const int c = n0 + wn * 32 + ni * 8 + (lane & 3) * 2;
            __half2 h0 = __floats2half2_rn(__expf(alpha * acc[mi][ni][0]),
                                           __expf(alpha * acc[mi][ni][1]));
            __half2 h1 = __floats2half2_rn(__expf(alpha * acc[mi][ni][2]),
                                           __expf(alpha * acc[mi][ni][3]));
            *(__half2*)(C + (size_t)r * NN + c)       = h0;
            *(__half2*)(C + (size_t)(r + 8) * NN + c) = h1;
            const float2 f0 = __half22float2(h0), f1 = __half22float2(h1);
            s0 += f0.x + f0.y;
            s1 += f1.x + f1.y;
        }
        // reduce across the 4 lanes of the quad (same row)
        s0 += __shfl_xor_sync(0xffffffffu, s0, 1);
        s0 += __shfl_xor_sync(0xffffffffu, s0, 2);
        s1 += __shfl_xor_sync(0xffffffffu, s1, 1);
        s1 += __shfl_xor_sync(0xffffffffu, s1, 2);
        if ((lane & 3) == 0) {
            atomicAdd(rs + r, s0);
            atomicAdd(rs + r + 8, s1);
        }
    }
}

// ---------------------------------------------------------------------------
// PV GEMM: out fp32 = (P @ V) / rowsum    (V supplied as V^T, K-major)
// ---------------------------------------------------------------------------
__global__ __launch_bounds__(256, 2)
void gemm_pv(const __half* __restrict__ Pg, const __half* __restrict__ Vt,
             float* __restrict__ Og, const float* __restrict__ rsum)
{
    extern __shared__ __align__(1024) char sm[];
    const int tid  = threadIdx.x;
    const int lane = tid & 31;
    const int warp = tid >> 5;
    const int wm = warp >> 2, wn = warp & 3;
    const int z = blockIdx.z;
    const __half* Ag = Pg + (size_t)z * NN * NN;
    const __half* Bg = Vt + (size_t)z * NN * DD;
    const int m0 = blockIdx.y * BM;
    const int n0 = blockIdx.x * BN;

    MAINLOOP_BODY(Ag, Bg, NN)

    float* C = Og + (size_t)z * NN * DD;
    const float* rs = rsum + z * NN;
#pragma unroll
    for (int mi = 0; mi < 4; mi++) {
        const int r = m0 + wm * 64 + mi * 16 + (lane >> 2);
        const float s0 = 1.0f / rs[r], s1 = 1.0f / rs[r + 8];
#pragma unroll
        for (int ni = 0; ni < 4; ni++) {
            const int c = n0 + wn * 32 + ni * 8 + (lane & 3) * 2;
            *(float2*)(C + (size_t)r * DD + c) =
                make_float2(s0 * acc[mi][ni][0], s0 * acc[mi][ni][1]);
            *(float2*)(C + (size_t)(r + 8) * DD + c) =
                make_float2(s1 * acc[mi][ni][2], s1 * acc[mi][ni][3]);
        }
    }
}

// ---------------------------------------------------------------------------
// Fused QKV GEMM: [8192,2304] = xh[8192,768] @ Wcat[2304,768]^T, fp16 out,
// routed to q/k/v by column block.
// ---------------------------------------------------------------------------
__global__ __launch_bounds__(256, 2)
void gemm_qkvF(const __half* __restrict__ Xh, const __half* __restrict__ Wc,
               __half* __restrict__ qp, __half* __restrict__ kp, __half* __restrict__ vp)
{
    extern __shared__ __align__(1024) char sm[];
    const int tid  = threadIdx.x;
    const int lane = tid & 31;
    const int warp = tid >> 5;
    const int wm = warp >> 2, wn = warp & 3;
    const __half* Ag = Xh;
    const __half* Bg = Wc;
    const int m0 = blockIdx.y * BM;
    const int n0 = blockIdx.x * BN;

    MAINLOOP_BODY(Ag, Bg, DD)

    const int w = n0 / DD;
    __half* dst = (w == 0) ? qp : ((w == 1) ? kp : vp);
    const int c0 = n0 - w * DD;
#pragma unroll
    for (int mi = 0; mi < 4; mi++) {
        const int r = m0 + wm * 64 + mi * 16 + (lane >> 2);
#pragma unroll
        for (int ni = 0; ni < 4; ni++) {
            const int c = c0 + wn * 32 + ni * 8 + (lane & 3) * 2;
            *(__half2*)(dst + (size_t)r * DD + c) =
                __floats2half2_rn(acc[mi][ni][0], acc[mi][ni][1]);
            *(__half2*)(dst + (size_t)(r + 8) * DD + c) =
                __floats2half2_rn(acc[mi][ni][2], acc[mi][ni][3]);
        }
    }
}

// ---------------------------------------------------------------------------
// x fp32 -> fp16
// ---------------------------------------------------------------------------
__global__ __launch_bounds__(256)
void convert_x(const float* __restrict__ x, __half* __restrict__ xh)
{
    const int i = blockIdx.x * 256 + threadIdx.x;
#pragma unroll
    for (int j = 0; j < 8; j++) {
        const int idx = i + j * gridDim.x * 256;
        const float4 f = *(const float4*)(x + idx * 4);
        uint2 u;
        u.x = h2u(__floats2half2_rn(f.x, f.y));
        u.y = h2u(__floats2half2_rn(f.z, f.w));
        *(uint2*)(xh + idx * 4) = u;
    }
}

// ---------------------------------------------------------------------------
// Weight prep: W[768,768] fp32 row-major ([K,N]) -> Wc[w][n][k] fp16 (transposed)
// ---------------------------------------------------------------------------
__global__ __launch_bounds__(256)
void prep_w(const float* __restrict__ w0, const float* __restrict__ w1,
            const float* __restrict__ w2, __half* __restrict__ wc)
{
    __shared__ float tile[32][33];
    const int z = blockIdx.z;
    const float* src = (z == 0) ? w0 : ((z == 1) ? w1 : w2);
    __half* dst = wc + (size_t)z * DD * DD;
    const int k0 = blockIdx.x * 32;
    const int n0 = blockIdx.y * 32;
    const int tid = threadIdx.x;
    const int r = tid >> 5, c = tid & 31;

#pragma unroll
    for (int i = 0; i < 4; i++)
        tile[r + i * 8][c] = src[(size_t)(k0 + r + i * 8) * DD + n0 + c];
    __syncthreads();
#pragma unroll
    for (int i = 0; i < 4; i++)
        dst[(size_t)(n0 + r + i * 8) * DD + k0 + c] = __float2half_rn(tile[c][r + i * 8]);
}

// ---------------------------------------------------------------------------
// fp16 transpose per batch: src [NN, DD] -> dst [DD, NN]
// ---------------------------------------------------------------------------
__global__ __launch_bounds__(256)
void transpose_h(const __half* __restrict__ src, __half* __restrict__ dst)
{
    __shared__ __half tile[64][65];
    const int z = blockIdx.z;
    src += (size_t)z * NN * DD;
    dst += (size_t)z * NN * DD;
    const int d0 = blockIdx.x * 64;
    const int t0 = blockIdx.y * 64;
    const int tid = threadIdx.x;

#pragma unroll
    for (int i = 0; i < 8; i++) {
        const int idx = tid + i * 256;
        const int r = idx >> 5, c2 = idx & 31;
        __half2 v = *(const __half2*)(src + (size_t)(t0 + r) * DD + d0 + c2 * 2);
        tile[r][c2 * 2]     = __low2half(v);
        tile[r][c2 * 2 + 1] = __high2half(v);
    }
    __syncthreads();
#pragma unroll
    for (int i = 0; i < 8; i++) {
        const int idx = tid + i * 256;
        const int dr = idx >> 5, c2 = idx & 31;
        __half2 v = __halves2half2(tile[c2 * 2][dr], tile[c2 * 2 + 1][dr]);
        *(__half2*)(dst + (size_t)(d0 + dr) * NN + t0 + c2 * 2) = v;
    }
}

// ---------------------------------------------------------------------------
extern "C" void kernel_launch(void* const* d_in, const int* in_sizes, int n_in,
                              void* d_out, int out_size)
{
    const float* x  = (const float*)d_in[0];
    const float* Wq = (const float*)d_in[1];
    const float* Wk = (const float*)d_in[2];
    const float* Wv = (const float*)d_in[3];
    float* out = (float*)d_out;

    __half *xh, *wc, *qh, *kh, *vh, *vt, *ph;
    float* rv;
    cudaGetSymbolAddress((void**)&xh, g_xh);
    cudaGetSymbolAddress((void**)&wc, g_wc);
    cudaGetSymbolAddress((void**)&qh, g_qh);
    cudaGetSymbolAddress((void**)&kh, g_kh);
    cudaGetSymbolAddress((void**)&vh, g_vh);
    cudaGetSymbolAddress((void**)&vt, g_vt);
    cudaGetSymbolAddress((void**)&ph, g_p);
    cudaGetSymbolAddress((void**)&rv, g_r);

    const int SMEM = NSTG * STG;   // 98304
    static bool attr_set = false;
    if (!attr_set) {
        cudaFuncSetAttribute(gemm_score, cudaFuncAttributeMaxDynamicSharedMemorySize, SMEM);
        cudaFuncSetAttribute(gemm_pv,    cudaFuncAttributeMaxDynamicSharedMemorySize, SMEM);
        cudaFuncSetAttribute(gemm_qkvF,  cudaFuncAttributeMaxDynamicSharedMemorySize, SMEM);
        attr_set = true;
    }

    const float scale = 0.03608439182435161f;  // 1/sqrt(768)
    const dim3 thr(256);

    // prep: x -> fp16 (6.29M elems = 1.57M float4, 8 per thread -> 768 blocks)
    convert_x<<<768, thr>>>(x, xh);
    prep_w<<<dim3(DD / 32, DD / 32, 3), thr>>>(Wq, Wk, Wv, wc);

    // fused QKV: [8192,2304] = xh @ wc^T
    gemm_qkvF<<<dim3(3 * DD / BN, BB * NN / BM, 1), thr, SMEM>>>(xh, wc, qh, kh, vh);

    // V^T per batch
    transpose_h<<<dim3(DD / 64, NN / 64, BB), thr>>>(vh, vt);

    // zero row sums, then score GEMM with fused rowsum atomics
    cudaMemsetAsync(rv, 0, BB * NN * sizeof(float));
    gemm_score<<<dim3(NN / BN, NN / BM, BB), thr, SMEM>>>(qh, kh, ph, rv, scale);

    // PV with fused normalization
    gemm_pv<<<dim3(DD / BN, NN / BM, BB), thr, SMEM>>>(ph, vt, out, rv);
}